// round 17
// baseline (speedup 1.0000x reference)
#include <cuda_runtime.h>
#include <cuda_fp16.h>
#include <cstddef>
#include <cstdint>

using f16 = __half;

// Problem constants
static constexpr int Bb    = 4;
static constexpr int Nn    = 4096;
static constexpr int Dd    = 1024;
static constexpr int Mrows = Bb * Nn;      // 16384
static constexpr int QKVN  = 3 * Dd;       // 3072
static constexpr int Kdim  = 1024;         // K of both GEMMs

// ---------------------------------------------------------------------------
// Scratch (__device__ globals; allocation-free rule)
// ---------------------------------------------------------------------------
__device__ f16 g_qkv16[(size_t)Mrows * QKVN];          // fp16 qkv (~100 MB)
__device__ f16 g_x16 [(size_t)Mrows * Dd];             // fp16(x)
__device__ f16 g_a16 [(size_t)Mrows * Dd];             // fp16(attn out)
__device__ f16 g_wq16[(size_t)QKVN * Dd];              // fp16(w_qkv)
__device__ f16 g_wf16[(size_t)Dd   * Dd];              // fp16(w_fc)

// ---------------------------------------------------------------------------
// Helpers
// ---------------------------------------------------------------------------
__device__ __forceinline__ uint32_t smem_u32(const void* p) {
    return (uint32_t)__cvta_generic_to_shared(p);
}
__device__ __forceinline__ void ldsm4(uint32_t& r0, uint32_t& r1,
                                      uint32_t& r2, uint32_t& r3, uint32_t addr) {
    asm volatile("ldmatrix.sync.aligned.m8n8.x4.shared.b16 {%0,%1,%2,%3}, [%4];\n"
                 : "=r"(r0), "=r"(r1), "=r"(r2), "=r"(r3) : "r"(addr));
}
__device__ __forceinline__ void mma_f16(float* c, const uint32_t* a, const uint32_t* b) {
    asm volatile(
        "mma.sync.aligned.m16n8k16.row.col.f32.f16.f16.f32 "
        "{%0,%1,%2,%3}, {%4,%5,%6,%7}, {%8,%9}, {%0,%1,%2,%3};\n"
        : "+f"(c[0]), "+f"(c[1]), "+f"(c[2]), "+f"(c[3])
        : "r"(a[0]), "r"(a[1]), "r"(a[2]), "r"(a[3]), "r"(b[0]), "r"(b[1]));
}
__device__ __forceinline__ void cp16(uint32_t dst, const void* src) {
    asm volatile("cp.async.cg.shared.global [%0], [%1], 16;" :: "r"(dst), "l"(src));
}
__device__ __forceinline__ void cp_commit() {
    asm volatile("cp.async.commit_group;" ::: "memory");
}
template <int N>
__device__ __forceinline__ void cp_wait() {
    asm volatile("cp.async.wait_group %0;" :: "n"(N) : "memory");
}
__device__ __forceinline__ uint2 pack4h(f16 a, f16 b, f16 c, f16 d) {
    uint2 r;
    uint16_t ua = *(uint16_t*)&a, ub = *(uint16_t*)&b;
    uint16_t uc = *(uint16_t*)&c, ud = *(uint16_t*)&d;
    r.x = (uint32_t)ua | ((uint32_t)ub << 16);
    r.y = (uint32_t)uc | ((uint32_t)ud << 16);
    return r;
}
__device__ __forceinline__ uint32_t pack2h(float a, float b) {
    f16 ha = __float2half_rn(a), hb = __float2half_rn(b);
    return (uint32_t)(*(uint16_t*)&ha) | ((uint32_t)(*(uint16_t*)&hb) << 16);
}

// ---------------------------------------------------------------------------
// fp16 tensor-core GEMM (NT), cp.async 3-stage pipeline, BK=64 stages
// (two 32-k sub-tiles per stage -> 64 mmas per sync pair).
//   C[m][n] = sum_k A16[m][k]*W16[n][k] (+bias); fp32 accumulate.
//   OUT16: emit fp16 (QKV path) or fp32 (final output).
// CTA 128x128, 8 warps (4m x 2n), warp tile 32m x 64n, m16n8k16.
// smem per stage: [A(k0..31) | A(k32..63) | W(k0..31) | W(k32..63)],
// each sub-tile 128 rows x 64 B, XOR swizzle chunk' = chunk ^ ((row>>1)&3).
// ---------------------------------------------------------------------------
static constexpr int BK      = 64;
static constexpr int KTILES  = Kdim / BK;        // 16
static constexpr int TSZ     = 128 * 64;          // 8192 B per sub-tile
static constexpr int STAGE   = 4 * TSZ;           // 32768 B
static constexpr int NSTAGE  = 3;
static constexpr int SMEM_TOTAL = NSTAGE * STAGE; // 98304 B

template <bool BIAS, bool OUT16>
__global__ __launch_bounds__(256, 2)
void gemm_cp(const f16* __restrict__ A16, const f16* __restrict__ W16,
             const float* __restrict__ bias,
             float* __restrict__ Cf, f16* __restrict__ Ch, int Ndim)
{
    extern __shared__ char smem[];
    const uint32_t smem_base = smem_u32(smem);
    const int tid  = threadIdx.x;
    const int wid  = tid >> 5;
    const int lane = tid & 31;
    const int wr   = wid & 3;           // m offset wr*32
    const int wc   = wid >> 2;          // n offset wc*64
    const int m0   = blockIdx.y * 128;
    const int n0   = blockIdx.x * 128;

    const f16* Ab = A16 + (size_t)m0 * Kdim;
    const f16* Wb = W16 + (size_t)n0 * Kdim;

    // ---- cp.async mapping (per thread: 8 chunks of 16 B per stage) ----
    // idx 0..2047: arr = idx>>9 (0=A lo-k, 1=A hi-k, 2=W lo-k, 3=W hi-k)
    auto load_stage = [&](int t, int buf) {
        const int k0 = t * BK;
        const uint32_t sb = smem_base + buf * STAGE;
        #pragma unroll
        for (int i = 0; i < 8; ++i) {
            const int idx = tid + i * 256;
            const int arr = idx >> 9;
            const int id2 = idx & 511;
            const int row = id2 >> 2;
            const int ch  = id2 & 3;
            const f16* src = (arr < 2) ? Ab : Wb;
            const int koff = k0 + (arr & 1) * 32 + ch * 8;
            const uint32_t dst = sb + arr * TSZ + row * 64 +
                                 ((ch ^ ((row >> 1) & 3)) << 4);
            cp16(dst, src + (size_t)row * Kdim + koff);
        }
        cp_commit();
    };

    // ---- ldmatrix offsets (within a 32-k sub-tile), per mi/gi and kk ----
    const int tq   = lane >> 3;
    const int arow = (lane & 7) + (tq & 1) * 8;
    const int ach  = tq >> 1;
    const int brow = (tq >> 1) * 8 + (lane & 7);
    const int bch  = tq & 1;

    uint32_t offA[2][2], offB[4][2];
    #pragma unroll
    for (int mi = 0; mi < 2; ++mi) {
        const int row = wr * 32 + mi * 16 + arow;
        #pragma unroll
        for (int kk = 0; kk < 2; ++kk) {
            const int ch = ach + kk * 2;
            offA[mi][kk] = row * 64 + (((ch ^ ((row >> 1) & 3))) << 4);
        }
    }
    #pragma unroll
    for (int gi = 0; gi < 4; ++gi) {
        const int row = wc * 64 + gi * 16 + brow;
        #pragma unroll
        for (int kk = 0; kk < 2; ++kk) {
            const int ch = bch + kk * 2;
            offB[gi][kk] = row * 64 + (((ch ^ ((row >> 1) & 3))) << 4);
        }
    }

    float acc[2][8][4];
    #pragma unroll
    for (int i = 0; i < 2; ++i)
        #pragma unroll
        for (int j = 0; j < 8; ++j)
            #pragma unroll
            for (int e = 0; e < 4; ++e) acc[i][j][e] = 0.f;

    // ---- prologue: fill the pipeline ----
    load_stage(0, 0);
    load_stage(1, 1);
    load_stage(2, 2);

    for (int t = 0; t < KTILES; ++t) {
        cp_wait<2>();              // stage t landed
        __syncthreads();

        const int buf = t % NSTAGE;
        const uint32_t sbase = smem_base + buf * STAGE;

        #pragma unroll
        for (int ks = 0; ks < 4; ++ks) {          // sub-tile (ks>>1), kk = ks&1
            const uint32_t sa = sbase + (ks >> 1) * TSZ;            // A sub
            const uint32_t sw = sbase + 2 * TSZ + (ks >> 1) * TSZ;  // W sub
            const int kk = ks & 1;
            uint32_t af[2][4], bfr[4][4];
            #pragma unroll
            for (int mi = 0; mi < 2; ++mi)
                ldsm4(af[mi][0], af[mi][1], af[mi][2], af[mi][3], sa + offA[mi][kk]);
            #pragma unroll
            for (int gi = 0; gi < 4; ++gi)
                ldsm4(bfr[gi][0], bfr[gi][1], bfr[gi][2], bfr[gi][3], sw + offB[gi][kk]);
            #pragma unroll
            for (int mi = 0; mi < 2; ++mi)
                #pragma unroll
                for (int g = 0; g < 8; ++g)
                    mma_f16(acc[mi][g], af[mi], &bfr[g >> 1][(g & 1) * 2]);
        }

        __syncthreads();
        if (t + NSTAGE < KTILES) load_stage(t + NSTAGE, buf);
    }

    // ---- epilogue (m16n8 C-frag layout) ----
    const int crow = lane >> 2;
    const int ccol = (lane & 3) * 2;
    #pragma unroll
    for (int mi = 0; mi < 2; ++mi) {
        #pragma unroll
        for (int g = 0; g < 8; ++g) {
            const int col = n0 + wc * 64 + g * 8 + ccol;
            const int r0  = m0 + wr * 32 + mi * 16 + crow;
            if (OUT16) {
                *(uint32_t*)(Ch + (size_t)r0 * Ndim + col) =
                    pack2h(acc[mi][g][0], acc[mi][g][1]);
                *(uint32_t*)(Ch + (size_t)(r0 + 8) * Ndim + col) =
                    pack2h(acc[mi][g][2], acc[mi][g][3]);
            } else {
                float b0 = BIAS ? bias[col]     : 0.f;
                float b1 = BIAS ? bias[col + 1] : 0.f;
                float2 v0 = make_float2(acc[mi][g][0] + b0, acc[mi][g][1] + b1);
                float2 v1 = make_float2(acc[mi][g][2] + b0, acc[mi][g][3] + b1);
                *(float2*)(Cf + (size_t)r0 * Ndim + col)       = v0;
                *(float2*)(Cf + (size_t)(r0 + 8) * Ndim + col) = v1;
            }
        }
    }
}

// ---------------------------------------------------------------------------
// Fused converts: x, w_qkv, w_fc -> fp16 (one launch)
// ---------------------------------------------------------------------------
static constexpr int N4X = Mrows * Dd / 4;   // x
static constexpr int N4Q = QKVN  * Dd / 4;   // w_qkv
static constexpr int N4F = Dd    * Dd / 4;   // w_fc
static constexpr int N4ALL = N4X + N4Q + N4F;

__device__ __forceinline__ void conv4h(const float* __restrict__ s,
                                       f16* __restrict__ h, int i) {
    float4 v = *(const float4*)(s + (size_t)i * 4);
    *(uint2*)(h + (size_t)i * 4) = pack4h(__float2half_rn(v.x), __float2half_rn(v.y),
                                          __float2half_rn(v.z), __float2half_rn(v.w));
}

__global__ void convert_all(const float* __restrict__ x,
                            const float* __restrict__ wq,
                            const float* __restrict__ wf,
                            f16* __restrict__ x16,
                            f16* __restrict__ wq16, f16* __restrict__ wf16)
{
    const int i = blockIdx.x * blockDim.x + threadIdx.x;
    if (i < N4X)               conv4h(x,  x16,  i);
    else if (i < N4X + N4Q)    conv4h(wq, wq16, i - N4X);
    else if (i < N4ALL)        conv4h(wf, wf16, i - N4X - N4Q);
}

// ---------------------------------------------------------------------------
// Attention (faithful-reshape 16x16 head-mixing), one CTA per (b, r, j):
//   q_prep[b, n, h, dh] = q[b, h*256 + n/16, (n%16)*64 + dh]
// fp16 qkv in (converted to fp32 in smem; math in fp32), fp16 out.
// ---------------------------------------------------------------------------
__global__ __launch_bounds__(256)
void attn16_kernel(const f16* __restrict__ qkv, f16* __restrict__ o16)
{
    const int bxi = blockIdx.x;          // b*4096 + r*16 + j
    const int j = bxi & 15;
    const int r = (bxi >> 4) & 255;
    const int b = bxi >> 12;
    const int tid = threadIdx.x;
    const int hh = tid >> 4;
    const int lo = tid & 15;

    __shared__ float qs[16][64];
    __shared__ float ks[16][65];
    __shared__ float vs[16][64];
    __shared__ float ps[16][17];

    const size_t rowbase = ((size_t)b * 4096 + (size_t)hh * 256 + r) * 3072;
    const size_t outbase = ((size_t)b * 4096 + (size_t)hh * 256 + r) * 1024;
    const float scale = 0.125f;

    {
        const size_t c = (size_t)j * 64 + lo * 4;
        uint2 qu = *(const uint2*)(qkv + rowbase + 0    + c);
        uint2 ku = *(const uint2*)(qkv + rowbase + 1024 + c);
        uint2 vu = *(const uint2*)(qkv + rowbase + 2048 + c);
        float2 q01 = __half22float2(*(__half2*)&qu.x);
        float2 q23 = __half22float2(*(__half2*)&qu.y);
        float2 k01 = __half22float2(*(__half2*)&ku.x);
        float2 k23 = __half22float2(*(__half2*)&ku.y);
        float2 v01 = __half22float2(*(__half2*)&vu.x);
        float2 v23 = __half22float2(*(__half2*)&vu.y);
        qs[hh][lo * 4 + 0] = q01.x; qs[hh][lo * 4 + 1] = q01.y;
        qs[hh][lo * 4 + 2] = q23.x; qs[hh][lo * 4 + 3] = q23.y;
        ks[hh][lo * 4 + 0] = k01.x; ks[hh][lo * 4 + 1] = k01.y;
        ks[hh][lo * 4 + 2] = k23.x; ks[hh][lo * 4 + 3] = k23.y;
        vs[hh][lo * 4 + 0] = v01.x; vs[hh][lo * 4 + 1] = v01.y;
        vs[hh][lo * 4 + 2] = v23.x; vs[hh][lo * 4 + 3] = v23.y;
    }
    __syncthreads();

    float s = 0.f;
    #pragma unroll
    for (int d = 0; d < 64; ++d) s = fmaf(qs[hh][d], ks[lo][d], s);
    s *= scale;

    float mx = s;
    #pragma unroll
    for (int off = 8; off; off >>= 1)
        mx = fmaxf(mx, __shfl_xor_sync(0xffffffffu, mx, off, 16));
    float e = __expf(s - mx);
    float sum = e;
    #pragma unroll
    for (int off = 8; off; off >>= 1)
        sum += __shfl_xor_sync(0xffffffffu, sum, off, 16);
    ps[hh][lo] = e / sum;
    __syncthreads();

    float4 o = make_float4(0.f, 0.f, 0.f, 0.f);
    #pragma unroll
    for (int g = 0; g < 16; ++g) {
        const float p = ps[hh][g];
        float4 v4 = *(const float4*)&vs[g][lo * 4];
        o.x = fmaf(p, v4.x, o.x); o.y = fmaf(p, v4.y, o.y);
        o.z = fmaf(p, v4.z, o.z); o.w = fmaf(p, v4.w, o.w);
    }
    *(uint2*)(o16 + outbase + (size_t)j * 64 + lo * 4) =
        pack4h(__float2half_rn(o.x), __float2half_rn(o.y),
               __float2half_rn(o.z), __float2half_rn(o.w));
}

// ---------------------------------------------------------------------------
// Launch
// ---------------------------------------------------------------------------
extern "C" void kernel_launch(void* const* d_in, const int* in_sizes, int n_in,
                              void* d_out, int out_size)
{
    const float* x     = (const float*)d_in[0];  // (4, 4096, 1024)
    const float* w_qkv = (const float*)d_in[1];  // (3072, 1024)
    const float* w_fc  = (const float*)d_in[2];  // (1024, 1024)
    const float* b_fc  = (const float*)d_in[3];  // (1024,)
    float* out = (float*)d_out;                  // (4, 4096, 1024)

    f16 *qkv_p, *x16_p, *a16_p, *wq_p, *wf_p;
    cudaGetSymbolAddress((void**)&qkv_p, g_qkv16);
    cudaGetSymbolAddress((void**)&x16_p, g_x16);
    cudaGetSymbolAddress((void**)&a16_p, g_a16);
    cudaGetSymbolAddress((void**)&wq_p,  g_wq16);
    cudaGetSymbolAddress((void**)&wf_p,  g_wf16);

    cudaFuncSetAttribute((const void*)gemm_cp<false,true>,
                         cudaFuncAttributeMaxDynamicSharedMemorySize, SMEM_TOTAL);
    cudaFuncSetAttribute((const void*)gemm_cp<true,false>,
                         cudaFuncAttributeMaxDynamicSharedMemorySize, SMEM_TOTAL);

    // 0) converts: x, w_qkv, w_fc -> fp16 (single fused launch)
    convert_all<<<(N4ALL + 255) / 256, 256>>>(x, w_qkv, w_fc, x16_p, wq_p, wf_p);

    // 1) qkv = x @ w_qkv^T  (fp16 out, M=16384, N=3072)
    gemm_cp<false,true><<<dim3(QKVN / 128, Mrows / 128), 256, SMEM_TOTAL>>>(
        x16_p, wq_p, nullptr, nullptr, qkv_p, QKVN);

    // 2) 16x16 head-mix attention -> fp16 (one CTA per (b,r,j))
    attn16_kernel<<<Bb * 256 * 16, 256>>>(qkv_p, a16_p);

    // 3) out = attn @ w_fc^T + b_fc  (fp32 out, M=16384, N=1024)
    gemm_cp<true,false><<<dim3(Dd / 128, Mrows / 128), 256, SMEM_TOTAL>>>(
        a16_p, wf_p, b_fc, out, nullptr, Dd);
}